// round 15
// baseline (speedup 1.0000x reference)
#include <cuda_runtime.h>
#include <cstdint>

// DepenL: out1[m] = Uk[m]*Uq[mc], out2[m] = Uk[mc]*Uq[m], mc = 9*(m/9)+4.
// m = p*L + l, U[m] = x[l/128 + p/3 - 1, l%128 + p%3 - 1] (0 outside).
// L mod 9 == 4 => center = same-plane pixel l + d, d = 4 - (m mod 9) in [-4,4].
// 2-wide vectorized, NT=512 / HC=32 for 3 CTAs/SM (48 warps resident).

#define WW   128
#define LL   16384
#define MM   147456
#define HC   32
#define NR   36        // HC + 2*2 halo rows
#define RS   136       // row stride floats
#define NT   512
#define SMN  (NR * RS)

__device__ __noinline__ float2 slow_center(const float* __restrict__ kb,
                                           const float* __restrict__ qb, int m) {
    const int g  = m / 9;
    const int mc = g * 9 + 4;
    const int pc = mc >> 14;
    const int lc = mc & 16383;
    const int ic = (pc * 11) >> 5;
    const int jc = pc - ic * 3;
    const int h  = (lc >> 7) + ic - 1;
    const int w  = (lc & 127) + jc - 1;
    if (((unsigned)h < 128u) && ((unsigned)w < 128u)) {
        const int gi = (h << 7) + w;
        return make_float2(__ldg(kb + gi), __ldg(qb + gi));
    }
    return make_float2(0.f, 0.f);
}

__global__ __launch_bounds__(NT, 3)
void depenl_v2w(const float* __restrict__ key, const float* __restrict__ query,
                float* __restrict__ out1, float* __restrict__ out2) {
    __shared__ float sK[SMN];
    __shared__ float sQ[SMN];

    const int bx    = blockIdx.x;
    const int ch    = bx >> 2;         // 0..255
    const int chunk = bx & 3;          // 0..3
    const int h0    = chunk * HC;
    const int l0    = h0 * WW;
    const int tid   = threadIdx.x;
    const int tid2  = tid * 2;

    const float* __restrict__ kb = key   + (size_t)ch * LL;
    const float* __restrict__ qb = query + (size_t)ch * LL;

    for (int idx = tid; idx < SMN; idx += NT) { sK[idx] = 0.f; sQ[idx] = 0.f; }
    __syncthreads();
    for (int t = tid; t < NR * 32; t += NT) {
        const int r = t >> 5, c4 = (t & 31) * 4;
        const int gh = h0 - 2 + r;
        if ((unsigned)gh < 128u) {
            *reinterpret_cast<float4*>(&sK[r * RS + 4 + c4]) =
                *reinterpret_cast<const float4*>(kb + gh * WW + c4);
            *reinterpret_cast<float4*>(&sQ[r * RS + 4 + c4]) =
                *reinterpret_cast<const float4*>(qb + gh * WW + c4);
        }
    }
    __syncthreads();

    float* const o1c = out1 + (size_t)ch * MM + l0 + tid2;
    float* const o2c = out2 + (size_t)ch * MM + l0 + tid2;

    int rp0 = (l0 + tid2) % 9;          // m mod 9 at p=0, it=0

    #pragma unroll
    for (int p = 0; p < 9; ++p) {
        const int i = (p * 11) >> 5;    // p/3  (constants after unroll)
        const int j = p - i * 3;        // p%3

        int r0 = rp0;
        #pragma unroll
        for (int it = 0; it < (HC * WW) / (2 * NT); ++it) {   // 4 iters
            const int l    = it * 1024 + tid2;                // local pixel, even
            const int nofs = ((l >> 7) + i + 1) * RS + (l & 127) + j + 3;

            float kn0, kn1, qn0, qn1;
            if (j == 1) {               // nofs even -> aligned float2
                const float2 k2 = *reinterpret_cast<const float2*>(&sK[nofs]);
                const float2 q2 = *reinterpret_cast<const float2*>(&sQ[nofs]);
                kn0 = k2.x; kn1 = k2.y; qn0 = q2.x; qn1 = q2.y;
            } else {
                kn0 = sK[nofs]; kn1 = sK[nofs + 1];
                qn0 = sQ[nofs]; qn1 = sQ[nofs + 1];
            }

            const int d0  = 4 - r0;
            const int lc0 = l + d0;             // group-0 center pixel (local)
            const int glc = l0 + lc0;
            float2 r1, r2;
            if ((unsigned)glc <= (unsigned)(LL - 10)) {
                const int c0  = ((lc0 >> 7) + i + 1) * RS + (lc0 & 127) + (j + 3);
                const int lc1 = lc0 + 9;
                const int c1  = ((lc1 >> 7) + i + 1) * RS + (lc1 & 127) + (j + 3);
                const float kc0 = sK[c0], qc0 = sQ[c0];
                const float kc1 = sK[c1], qc1 = sQ[c1];
                const float kB = (r0 < 8) ? kc0 : kc1;
                const float qB = (r0 < 8) ? qc0 : qc1;
                r1.x = kn0 * qc0;  r2.x = kc0 * qn0;
                r1.y = kn1 * qB;   r2.y = kB  * qn1;
            } else {
                const int mbase = p * LL + l0 + l;
                const float2 c0 = slow_center(kb, qb, mbase + 0);
                const float2 c1 = slow_center(kb, qb, mbase + 1);
                r1.x = kn0 * c0.y;  r2.x = c0.x * qn0;
                r1.y = kn1 * c1.y;  r2.y = c1.x * qn1;
            }

            __stcs(reinterpret_cast<float2*>(o1c + p * LL + it * 1024), r1);
            __stcs(reinterpret_cast<float2*>(o2c + p * LL + it * 1024), r2);

            r0 += 7; if (r0 >= 9) r0 -= 9;     // m += 1024 (1024 mod 9 = 7)
        }
        rp0 += 4; if (rp0 >= 9) rp0 -= 9;      // m += L (L mod 9 = 4)
    }
}

extern "C" void kernel_launch(void* const* d_in, const int* in_sizes, int n_in,
                              void* d_out, int out_size) {
    const float* key   = (const float*)d_in[0];
    const float* query = (const float*)d_in[1];
    float* out1 = (float*)d_out;
    float* out2 = out1 + (size_t)256 * MM;

    depenl_v2w<<<256 * 4, NT>>>(key, query, out1, out2);
}